// round 1
// baseline (speedup 1.0000x reference)
#include <cuda_runtime.h>

#define NTOT   12288
#define DIN    512
#define DIM    512
#define HEADS  8
#define DHEAD  64
#define NBATCH 32
#define NMAXQT 8          // NMAX/64 query tiles

// ---------------- scratch (device globals; no allocation allowed) ----------------
__device__ float g_zn[NTOT * DIN];
__device__ float g_q [NTOT * DIM];
__device__ float g_k [NTOT * DIM];
__device__ float g_v [NTOT * DIM];
__device__ float g_o [NTOT * DIM];
__device__ int   g_starts[NBATCH + 1];

// ---------------- graph offsets: src is sorted, starts[b] = lower_bound(src, b) ----
__global__ void starts_kernel(const int* __restrict__ src) {
    int b = threadIdx.x;
    if (b > NBATCH) return;
    int lo = 0, hi = NTOT;
    while (lo < hi) {
        int mid = (lo + hi) >> 1;
        if (src[mid] < b) lo = mid + 1; else hi = mid;
    }
    g_starts[b] = lo;
}

// ---------------- LayerNorm over 512 dims, one block (128 thr) per row ------------
__global__ void __launch_bounds__(128) ln_kernel(const float* __restrict__ z,
                                                 const float* __restrict__ gamma,
                                                 const float* __restrict__ beta) {
    __shared__ float red[8];
    const int row = blockIdx.x;
    const int t = threadIdx.x;                  // 128 threads, 1 float4 each
    float4 v = ((const float4*)(z + (size_t)row * DIN))[t];
    float s  = v.x + v.y + v.z + v.w;
    float ss = v.x*v.x + v.y*v.y + v.z*v.z + v.w*v.w;
    #pragma unroll
    for (int off = 16; off; off >>= 1) {
        s  += __shfl_xor_sync(0xffffffffu, s,  off);
        ss += __shfl_xor_sync(0xffffffffu, ss, off);
    }
    const int w = t >> 5;
    if ((t & 31) == 0) { red[w] = s; red[4 + w] = ss; }
    __syncthreads();
    s  = red[0] + red[1] + red[2] + red[3];
    ss = red[4] + red[5] + red[6] + red[7];
    const float mu  = s * (1.0f / DIN);
    const float var = ss * (1.0f / DIN) - mu * mu;
    const float inv = rsqrtf(var + 1e-5f);
    float4 g  = ((const float4*)gamma)[t];
    float4 be = ((const float4*)beta)[t];
    float4 o;
    o.x = (v.x - mu) * inv * g.x + be.x;
    o.y = (v.y - mu) * inv * g.y + be.y;
    o.z = (v.z - mu) * inv * g.z + be.z;
    o.w = (v.w - mu) * inv * g.w + be.w;
    ((float4*)(g_zn + (size_t)row * DIN))[t] = o;
}

// ---------------- SGEMM: C[M,512] = A[M,512] @ W[512,512] (+bias) -----------------
// Tile 128(M) x 64(N) x 16(K), 256 threads, 8x4 per-thread microtile.
template<bool BIAS>
__global__ void __launch_bounds__(256) sgemm_kernel(const float* __restrict__ A,
                                                    const float* __restrict__ W,
                                                    float* __restrict__ C,
                                                    const float* __restrict__ bias) {
    __shared__ float As[16][132];   // A transposed in smem: As[k][m]
    __shared__ float Bs[16][68];    // Bs[k][n]
    const int tid = threadIdx.x;
    const int ty = tid >> 4, tx = tid & 15;
    const int mBase = blockIdx.y * 128;
    const int nBase = blockIdx.x * 64;
    float acc[8][4] = {};
    for (int kb = 0; kb < DIN; kb += 16) {
        #pragma unroll
        for (int r = 0; r < 2; r++) {
            int l = tid + r * 256;            // 0..511
            int row = l >> 2;                 // 0..127
            int k4 = (l & 3) << 2;            // 0,4,8,12
            float4 av = *(const float4*)&A[(size_t)(mBase + row) * DIN + kb + k4];
            As[k4 + 0][row] = av.x; As[k4 + 1][row] = av.y;
            As[k4 + 2][row] = av.z; As[k4 + 3][row] = av.w;
        }
        {
            int k = tid >> 4;                 // 0..15
            int n4 = (tid & 15) << 2;         // 0..60
            *(float4*)&Bs[k][n4] = *(const float4*)&W[(size_t)(kb + k) * DIM + nBase + n4];
        }
        __syncthreads();
        #pragma unroll
        for (int k = 0; k < 16; k++) {
            float a0[8], b0[4];
            *(float4*)&a0[0] = *(const float4*)&As[k][ty * 8];
            *(float4*)&a0[4] = *(const float4*)&As[k][ty * 8 + 4];
            *(float4*)&b0[0] = *(const float4*)&Bs[k][tx * 4];
            #pragma unroll
            for (int i = 0; i < 8; i++)
                #pragma unroll
                for (int j = 0; j < 4; j++)
                    acc[i][j] = fmaf(a0[i], b0[j], acc[i][j]);
        }
        __syncthreads();
    }
    #pragma unroll
    for (int i = 0; i < 8; i++) {
        float4 o = make_float4(acc[i][0], acc[i][1], acc[i][2], acc[i][3]);
        if (BIAS) {
            float4 bb = *(const float4*)&bias[nBase + tx * 4];
            o.x += bb.x; o.y += bb.y; o.z += bb.z; o.w += bb.w;
        }
        *(float4*)&C[(size_t)(mBase + ty * 8 + i) * DIM + nBase + tx * 4] = o;
    }
}

// ---------------- per-graph flash attention --------------------------------------
// Block = 64 queries of (graph b, head h); loops keys in chunks of 64.
// 256 threads, 4x4 register tiles; row groups = half-warps (shfl width 16).
#define APAD 68
#define ATTN_SMEM (4 * 64 * APAD * 4)

__global__ void __launch_bounds__(256) attn_kernel() {
    extern __shared__ float sm[];
    float* Qst = sm;                    // [64][68]  Qst[d][m]
    float* Kst = sm + 64 * APAD;        // [64][68]  Kst[d][n]
    float* Vsm = sm + 2 * 64 * APAD;    // [64][68]  Vsm[n][d]
    float* Pst = sm + 3 * 64 * APAD;    // [64][68]  Pst[n][m]
    const int qt = blockIdx.x, h = blockIdx.y, b = blockIdx.z;
    const int s0 = g_starts[b];
    const int ng = g_starts[b + 1] - s0;
    const int q0 = qt * 64;
    if (q0 >= ng) return;
    const int tid = threadIdx.x;
    const int ty = tid >> 4, tx = tid & 15;

    // Load Q tile transposed (pad rows -> 0)
    #pragma unroll
    for (int r = 0; r < 4; r++) {
        int l = tid + r * 256;
        int m = l >> 4;
        int d4 = (l & 15) << 2;
        float4 qv = make_float4(0.f, 0.f, 0.f, 0.f);
        if (q0 + m < ng)
            qv = *(const float4*)&g_q[(size_t)(s0 + q0 + m) * DIM + h * DHEAD + d4];
        Qst[(d4 + 0) * APAD + m] = qv.x; Qst[(d4 + 1) * APAD + m] = qv.y;
        Qst[(d4 + 2) * APAD + m] = qv.z; Qst[(d4 + 3) * APAD + m] = qv.w;
    }

    float acc[4][4] = {};
    float rm[4] = {-1e30f, -1e30f, -1e30f, -1e30f};
    float rl[4] = {};

    for (int kb = 0; kb < ng; kb += 64) {
        // Load K (transposed) + V (natural), guarded against range end
        #pragma unroll
        for (int r = 0; r < 4; r++) {
            int l = tid + r * 256;
            int n = l >> 4;
            int d4 = (l & 15) << 2;
            float4 kv = make_float4(0.f, 0.f, 0.f, 0.f);
            float4 vv = make_float4(0.f, 0.f, 0.f, 0.f);
            if (kb + n < ng) {
                size_t base = (size_t)(s0 + kb + n) * DIM + h * DHEAD + d4;
                kv = *(const float4*)&g_k[base];
                vv = *(const float4*)&g_v[base];
            }
            Kst[(d4 + 0) * APAD + n] = kv.x; Kst[(d4 + 1) * APAD + n] = kv.y;
            Kst[(d4 + 2) * APAD + n] = kv.z; Kst[(d4 + 3) * APAD + n] = kv.w;
            *(float4*)&Vsm[n * APAD + d4] = vv;
        }
        __syncthreads();

        // S = Q K^T (64x64 tile in registers)
        float sv[4][4] = {};
        #pragma unroll
        for (int d = 0; d < 64; d++) {
            float a0[4], b0[4];
            *(float4*)a0 = *(const float4*)&Qst[d * APAD + ty * 4];
            *(float4*)b0 = *(const float4*)&Kst[d * APAD + tx * 4];
            #pragma unroll
            for (int i = 0; i < 4; i++)
                #pragma unroll
                for (int j = 0; j < 4; j++)
                    sv[i][j] = fmaf(a0[i], b0[j], sv[i][j]);
        }

        // online softmax per row (row group = half warp, shfl width 16)
        #pragma unroll
        for (int i = 0; i < 4; i++) {
            #pragma unroll
            for (int j = 0; j < 4; j++) {
                int kk = kb + tx * 4 + j;
                sv[i][j] = (kk < ng) ? sv[i][j] * 0.125f : -1e30f;
            }
            float cm = fmaxf(fmaxf(sv[i][0], sv[i][1]), fmaxf(sv[i][2], sv[i][3]));
            cm = fmaxf(cm, __shfl_xor_sync(0xffffffffu, cm, 8, 16));
            cm = fmaxf(cm, __shfl_xor_sync(0xffffffffu, cm, 4, 16));
            cm = fmaxf(cm, __shfl_xor_sync(0xffffffffu, cm, 2, 16));
            cm = fmaxf(cm, __shfl_xor_sync(0xffffffffu, cm, 1, 16));
            float nm = fmaxf(rm[i], cm);
            float sc = __expf(rm[i] - nm);
            rm[i] = nm;
            float cl = 0.f;
            #pragma unroll
            for (int j = 0; j < 4; j++) {
                float p = __expf(sv[i][j] - nm);
                sv[i][j] = p;
                cl += p;
            }
            cl += __shfl_xor_sync(0xffffffffu, cl, 8, 16);
            cl += __shfl_xor_sync(0xffffffffu, cl, 4, 16);
            cl += __shfl_xor_sync(0xffffffffu, cl, 2, 16);
            cl += __shfl_xor_sync(0xffffffffu, cl, 1, 16);
            rl[i] = rl[i] * sc + cl;
            #pragma unroll
            for (int j = 0; j < 4; j++) acc[i][j] *= sc;
        }

        // scatter P transposed to smem (prev PV finished at loop-end sync)
        #pragma unroll
        for (int i = 0; i < 4; i++)
            #pragma unroll
            for (int j = 0; j < 4; j++)
                Pst[(tx * 4 + j) * APAD + ty * 4 + i] = sv[i][j];
        __syncthreads();

        // O += P V
        #pragma unroll
        for (int n = 0; n < 64; n++) {
            float a0[4], b0[4];
            *(float4*)a0 = *(const float4*)&Pst[n * APAD + ty * 4];
            *(float4*)b0 = *(const float4*)&Vsm[n * APAD + tx * 4];
            #pragma unroll
            for (int i = 0; i < 4; i++)
                #pragma unroll
                for (int j = 0; j < 4; j++)
                    acc[i][j] = fmaf(a0[i], b0[j], acc[i][j]);
        }
        __syncthreads();
    }

    // epilogue: normalize + store valid rows
    #pragma unroll
    for (int i = 0; i < 4; i++) {
        int m = q0 + ty * 4 + i;
        if (m < ng) {
            float inv = 1.f / rl[i];
            float4 o = make_float4(acc[i][0] * inv, acc[i][1] * inv,
                                   acc[i][2] * inv, acc[i][3] * inv);
            *(float4*)&g_o[(size_t)(s0 + m) * DIM + h * DHEAD + tx * 4] = o;
        }
    }
}

// ---------------- launch ----------------------------------------------------------
extern "C" void kernel_launch(void* const* d_in, const int* in_sizes, int n_in,
                              void* d_out, int out_size) {
    const float* z     = (const float*)d_in[0];
    const int*   src   = (const int*)  d_in[1];
    const float* gamma = (const float*)d_in[2];
    const float* beta  = (const float*)d_in[3];
    const float* Wq    = (const float*)d_in[4];
    const float* Wk    = (const float*)d_in[5];
    const float* Wv    = (const float*)d_in[6];
    const float* Wo    = (const float*)d_in[7];
    const float* bo    = (const float*)d_in[8];
    float* out = (float*)d_out;

    cudaFuncSetAttribute(attn_kernel, cudaFuncAttributeMaxDynamicSharedMemorySize, ATTN_SMEM);

    float *zn_p, *q_p, *k_p, *v_p, *o_p;
    cudaGetSymbolAddress((void**)&zn_p, g_zn);
    cudaGetSymbolAddress((void**)&q_p,  g_q);
    cudaGetSymbolAddress((void**)&k_p,  g_k);
    cudaGetSymbolAddress((void**)&v_p,  g_v);
    cudaGetSymbolAddress((void**)&o_p,  g_o);

    starts_kernel<<<1, 64>>>(src);
    ln_kernel<<<NTOT, 128>>>(z, gamma, beta);

    dim3 ggrid(DIM / 64, NTOT / 128);
    sgemm_kernel<false><<<ggrid, 256>>>(zn_p, Wq, q_p, nullptr);
    sgemm_kernel<false><<<ggrid, 256>>>(zn_p, Wk, k_p, nullptr);
    sgemm_kernel<false><<<ggrid, 256>>>(zn_p, Wv, v_p, nullptr);

    dim3 agrid(NMAXQT, HEADS, NBATCH);
    attn_kernel<<<agrid, 256, ATTN_SMEM>>>();

    sgemm_kernel<true><<<ggrid, 256>>>(o_p, Wo, out, bo);
}

// round 3
// speedup vs baseline: 1.6939x; 1.6939x over previous
#include <cuda_runtime.h>
#include <cuda_bf16.h>
#include <cstdint>

#define NTOT   12288
#define DIN    512
#define DIM    512
#define HEADS  8
#define DHEAD  64
#define NBATCH 32
#define NMAXQT 8

// ======================= warp-MMA helpers (sm_80 ISA, works at compute_103) =====
__device__ __forceinline__ uint32_t smem_u32(const void* p) {
    uint32_t a;
    asm("{ .reg .u64 t; cvta.to.shared.u64 t, %1; cvt.u32.u64 %0, t; }" : "=r"(a) : "l"(p));
    return a;
}
__device__ __forceinline__ void ldsm4(uint32_t* r, uint32_t addr) {
    asm volatile("ldmatrix.sync.aligned.m8n8.x4.shared.b16 {%0,%1,%2,%3}, [%4];"
        : "=r"(r[0]), "=r"(r[1]), "=r"(r[2]), "=r"(r[3]) : "r"(addr));
}
__device__ __forceinline__ void mma16816(float* c, const uint32_t* a,
                                         uint32_t b0, uint32_t b1) {
    asm volatile("mma.sync.aligned.m16n8k16.row.col.f32.bf16.bf16.f32 "
        "{%0,%1,%2,%3}, {%4,%5,%6,%7}, {%8,%9}, {%0,%1,%2,%3};"
        : "+f"(c[0]), "+f"(c[1]), "+f"(c[2]), "+f"(c[3])
        : "r"(a[0]), "r"(a[1]), "r"(a[2]), "r"(a[3]), "r"(b0), "r"(b1));
}

// ======================= scratch =================================================
__device__ __nv_bfloat16 g_ahi[NTOT * DIN];
__device__ __nv_bfloat16 g_alo[NTOT * DIN];
__device__ __nv_bfloat16 g_wthi[4 * DIN * DIM];   // [mat][n][k]
__device__ __nv_bfloat16 g_wtlo[4 * DIN * DIM];
__device__ float g_q[NTOT * DIM];
__device__ float g_k[NTOT * DIM];
__device__ float g_v[NTOT * DIM];
__device__ float g_o[NTOT * DIM];
__device__ int   g_starts[NBATCH + 1];

// ======================= starts ==================================================
__global__ void starts_kernel(const int* __restrict__ src) {
    int b = threadIdx.x;
    if (b > NBATCH) return;
    int lo = 0, hi = NTOT;
    while (lo < hi) { int mid = (lo + hi) >> 1; if (src[mid] < b) lo = mid + 1; else hi = mid; }
    g_starts[b] = lo;
}

// ======================= LayerNorm -> split bf16 =================================
__global__ void __launch_bounds__(128) ln_kernel(const float* __restrict__ z,
                                                 const float* __restrict__ gamma,
                                                 const float* __restrict__ beta) {
    __shared__ float red[8];
    const int row = blockIdx.x;
    const int t = threadIdx.x;
    float4 v = ((const float4*)(z + (size_t)row * DIN))[t];
    float s  = v.x + v.y + v.z + v.w;
    float ss = v.x*v.x + v.y*v.y + v.z*v.z + v.w*v.w;
    #pragma unroll
    for (int off = 16; off; off >>= 1) {
        s  += __shfl_xor_sync(0xffffffffu, s,  off);
        ss += __shfl_xor_sync(0xffffffffu, ss, off);
    }
    const int w = t >> 5;
    if ((t & 31) == 0) { red[w] = s; red[4 + w] = ss; }
    __syncthreads();
    s  = red[0] + red[1] + red[2] + red[3];
    ss = red[4] + red[5] + red[6] + red[7];
    const float mu  = s * (1.0f / DIN);
    const float var = ss * (1.0f / DIN) - mu * mu;
    const float inv = rsqrtf(var + 1e-5f);
    float4 g  = ((const float4*)gamma)[t];
    float4 be = ((const float4*)beta)[t];
    float o[4];
    o[0] = (v.x - mu) * inv * g.x + be.x;
    o[1] = (v.y - mu) * inv * g.y + be.y;
    o[2] = (v.z - mu) * inv * g.z + be.z;
    o[3] = (v.w - mu) * inv * g.w + be.w;
    __nv_bfloat16 hi[4], lo[4];
    #pragma unroll
    for (int i = 0; i < 4; i++) {
        hi[i] = __float2bfloat16(o[i]);
        lo[i] = __float2bfloat16(o[i] - __bfloat162float(hi[i]));
    }
    size_t base = (size_t)row * DIN + t * 4;
    *(__nv_bfloat162*)&g_ahi[base]     = *(__nv_bfloat162*)&hi[0];
    *(__nv_bfloat162*)&g_ahi[base + 2] = *(__nv_bfloat162*)&hi[2];
    *(__nv_bfloat162*)&g_alo[base]     = *(__nv_bfloat162*)&lo[0];
    *(__nv_bfloat162*)&g_alo[base + 2] = *(__nv_bfloat162*)&lo[2];
}

// ======================= weight transpose + split ================================
__global__ void __launch_bounds__(256) wconv_kernel(const float* __restrict__ Wq,
                                                    const float* __restrict__ Wk,
                                                    const float* __restrict__ Wv,
                                                    const float* __restrict__ Wo) {
    __shared__ float t[32][33];
    const float* W = blockIdx.z == 0 ? Wq : blockIdx.z == 1 ? Wk : blockIdx.z == 2 ? Wv : Wo;
    const int bx = blockIdx.x, by = blockIdx.y;
    const int tx = threadIdx.x, ty = threadIdx.y;    // 32 x 8
    #pragma unroll
    for (int i = 0; i < 4; i++)
        t[ty + 8 * i][tx] = W[(size_t)(by * 32 + ty + 8 * i) * DIM + bx * 32 + tx];
    __syncthreads();
    size_t mbase = (size_t)blockIdx.z * DIN * DIM;
    #pragma unroll
    for (int i = 0; i < 4; i++) {
        int n = bx * 32 + ty + 8 * i;
        int k = by * 32 + tx;
        float v = t[tx][ty + 8 * i];
        __nv_bfloat16 hi = __float2bfloat16(v);
        __nv_bfloat16 lo = __float2bfloat16(v - __bfloat162float(hi));
        g_wthi[mbase + (size_t)n * DIN + k] = hi;
        g_wtlo[mbase + (size_t)n * DIN + k] = lo;
    }
}

// ======================= attention output -> split bf16 ==========================
__global__ void __launch_bounds__(256) oconv_kernel() {
    int i = blockIdx.x * 256 + threadIdx.x;
    float4 v = ((const float4*)g_o)[i];
    float o[4] = {v.x, v.y, v.z, v.w};
    __nv_bfloat16 hi[4], lo[4];
    #pragma unroll
    for (int j = 0; j < 4; j++) {
        hi[j] = __float2bfloat16(o[j]);
        lo[j] = __float2bfloat16(o[j] - __bfloat162float(hi[j]));
    }
    size_t base = (size_t)i * 4;
    *(__nv_bfloat162*)&g_ahi[base]     = *(__nv_bfloat162*)&hi[0];
    *(__nv_bfloat162*)&g_ahi[base + 2] = *(__nv_bfloat162*)&hi[2];
    *(__nv_bfloat162*)&g_alo[base]     = *(__nv_bfloat162*)&lo[0];
    *(__nv_bfloat162*)&g_alo[base + 2] = *(__nv_bfloat162*)&lo[2];
}

// ======================= mma.sync split-bf16 GEMM ================================
// C[12288,512] = (Ahi+Alo)@(Whi+Wlo)  CTA tile 128x128, k-chunk 64, 8 warps.
// smem rows padded to 72 bf16 (144B): ldmatrix rows land on distinct bank quads.
#define GLDS 72
#define G_TILE_B (128 * GLDS * 2)      // 18432 B per tile
#define G_SMEM_TOT (4 * G_TILE_B)      // 73728 B

template<bool BIAS>
__global__ void __launch_bounds__(256, 2)
gemm_mma(const __nv_bfloat16* __restrict__ Ahi, const __nv_bfloat16* __restrict__ Alo,
         const __nv_bfloat16* __restrict__ Wthi, const __nv_bfloat16* __restrict__ Wtlo,
         float* o0, float* o1, float* o2, const float* __restrict__ bias) {
    extern __shared__ char smem[];
    char* sAhi = smem;
    char* sAlo = smem + G_TILE_B;
    char* sWhi = smem + 2 * G_TILE_B;
    char* sWlo = smem + 3 * G_TILE_B;
    const int tid  = threadIdx.x;
    const int wid  = tid >> 5;
    const int lane = tid & 31;
    const int mwarp = wid & 3;           // warp m offset = mwarp*32
    const int nwarp = wid >> 2;          // warp n offset = nwarp*64
    const int nBase = blockIdx.x * 128;
    const int mBase = blockIdx.y * 128;
    const int mat = blockIdx.z;
    float* out = (mat == 0) ? o0 : (mat == 1) ? o1 : o2;
    const __nv_bfloat16* whi = Wthi + (size_t)mat * DIN * DIM + (size_t)nBase * DIN;
    const __nv_bfloat16* wlo = Wtlo + (size_t)mat * DIN * DIM + (size_t)nBase * DIN;
    const __nv_bfloat16* ahi = Ahi + (size_t)mBase * DIN;
    const __nv_bfloat16* alo = Alo + (size_t)mBase * DIN;

    const uint32_t sb = smem_u32(smem);
    // ldmatrix lane addr offsets (row = lane&15, col-half = lane>>4)
    const int lrow = lane & 15;
    const int lcol = (lane >> 4) * 8;

    float acc[2][8][4];
    #pragma unroll
    for (int a = 0; a < 2; a++)
        #pragma unroll
        for (int b = 0; b < 8; b++)
            #pragma unroll
            for (int c = 0; c < 4; c++) acc[a][b][c] = 0.f;

    const __nv_bfloat16* gsrc[4] = { ahi, alo, whi, wlo };

    for (int kb = 0; kb < DIN; kb += 64) {
        #pragma unroll
        for (int t = 0; t < 4; t++) {
            const __nv_bfloat16* gp = gsrc[t] + kb;
            char* sp = smem + t * G_TILE_B;
            #pragma unroll
            for (int r = 0; r < 4; r++) {
                int idx = tid + r * 256;          // 0..1023
                int row = idx >> 3;               // 0..127
                int j   = idx & 7;                // 16B units (8 bf16)
                uint4 v = *(const uint4*)(gp + (size_t)row * DIN + j * 8);
                *(uint4*)(sp + row * (GLDS * 2) + j * 16) = v;
            }
        }
        __syncthreads();

        #pragma unroll
        for (int ks = 0; ks < 4; ks++) {
            const int kk = ks * 16 + lcol;
            uint32_t ah[2][4], al[2][4];
            #pragma unroll
            for (int mt = 0; mt < 2; mt++) {
                uint32_t off = (uint32_t)((mwarp * 32 + mt * 16 + lrow) * GLDS + kk) * 2;
                ldsm4(ah[mt], sb + off);                         // sAhi at offset 0
                ldsm4(al[mt], sb + G_TILE_B + off);
            }
            #pragma unroll
            for (int nb = 0; nb < 4; nb++) {
                uint32_t off = (uint32_t)((nwarp * 64 + nb * 16 + lrow) * GLDS + kk) * 2;
                uint32_t bh[4], bl[4];
                ldsm4(bh, sb + 2 * G_TILE_B + off);
                ldsm4(bl, sb + 3 * G_TILE_B + off);
                #pragma unroll
                for (int mt = 0; mt < 2; mt++) {
                    float* c0 = acc[mt][2 * nb];
                    float* c1 = acc[mt][2 * nb + 1];
                    mma16816(c0, ah[mt], bh[0], bh[2]);
                    mma16816(c0, ah[mt], bl[0], bl[2]);
                    mma16816(c0, al[mt], bh[0], bh[2]);
                    mma16816(c1, ah[mt], bh[1], bh[3]);
                    mma16816(c1, ah[mt], bl[1], bl[3]);
                    mma16816(c1, al[mt], bh[1], bh[3]);
                }
            }
        }
        __syncthreads();
    }

    // epilogue: c0,c1 -> (m = base + lane/4, n = n8*8 + 2*(lane%4)); c2,c3 at m+8
    const int erow = lane >> 2;
    const int ecol = (lane & 3) * 2;
    #pragma unroll
    for (int mt = 0; mt < 2; mt++) {
        int r0 = mBase + mwarp * 32 + mt * 16 + erow;
        #pragma unroll
        for (int n8 = 0; n8 < 8; n8++) {
            int col = nBase + nwarp * 64 + n8 * 8 + ecol;
            float2 v0 = make_float2(acc[mt][n8][0], acc[mt][n8][1]);
            float2 v1 = make_float2(acc[mt][n8][2], acc[mt][n8][3]);
            if (BIAS) {
                float2 bb = *(const float2*)&bias[col];
                v0.x += bb.x; v0.y += bb.y;
                v1.x += bb.x; v1.y += bb.y;
            }
            *(float2*)&out[(size_t)r0 * DIM + col]       = v0;
            *(float2*)&out[(size_t)(r0 + 8) * DIM + col] = v1;
        }
    }
}

// ======================= per-graph flash attention (fp32) ========================
#define APAD 68
#define ATTN_SMEM (4 * 64 * APAD * 4)

__global__ void __launch_bounds__(256) attn_kernel() {
    extern __shared__ float sm[];
    float* Qst = sm;
    float* Kst = sm + 64 * APAD;
    float* Vsm = sm + 2 * 64 * APAD;
    float* Pst = sm + 3 * 64 * APAD;
    const int qt = blockIdx.x, h = blockIdx.y, b = blockIdx.z;
    const int s0 = g_starts[b];
    const int ng = g_starts[b + 1] - s0;
    const int q0 = qt * 64;
    if (q0 >= ng) return;
    const int tid = threadIdx.x;
    const int ty = tid >> 4, tx = tid & 15;

    #pragma unroll
    for (int r = 0; r < 4; r++) {
        int l = tid + r * 256;
        int m = l >> 4;
        int d4 = (l & 15) << 2;
        float4 qv = make_float4(0.f, 0.f, 0.f, 0.f);
        if (q0 + m < ng)
            qv = *(const float4*)&g_q[(size_t)(s0 + q0 + m) * DIM + h * DHEAD + d4];
        Qst[(d4 + 0) * APAD + m] = qv.x; Qst[(d4 + 1) * APAD + m] = qv.y;
        Qst[(d4 + 2) * APAD + m] = qv.z; Qst[(d4 + 3) * APAD + m] = qv.w;
    }

    float acc[4][4] = {};
    float rm[4] = {-1e30f, -1e30f, -1e30f, -1e30f};
    float rl[4] = {};

    for (int kb = 0; kb < ng; kb += 64) {
        #pragma unroll
        for (int r = 0; r < 4; r++) {
            int l = tid + r * 256;
            int n = l >> 4;
            int d4 = (l & 15) << 2;
            float4 kv = make_float4(0.f, 0.f, 0.f, 0.f);
            float4 vv = make_float4(0.f, 0.f, 0.f, 0.f);
            if (kb + n < ng) {
                size_t base = (size_t)(s0 + kb + n) * DIM + h * DHEAD + d4;
                kv = *(const float4*)&g_k[base];
                vv = *(const float4*)&g_v[base];
            }
            Kst[(d4 + 0) * APAD + n] = kv.x; Kst[(d4 + 1) * APAD + n] = kv.y;
            Kst[(d4 + 2) * APAD + n] = kv.z; Kst[(d4 + 3) * APAD + n] = kv.w;
            *(float4*)&Vsm[n * APAD + d4] = vv;
        }
        __syncthreads();

        float sv[4][4] = {};
        #pragma unroll
        for (int d = 0; d < 64; d++) {
            float a0[4], b0[4];
            *(float4*)a0 = *(const float4*)&Qst[d * APAD + ty * 4];
            *(float4*)b0 = *(const float4*)&Kst[d * APAD + tx * 4];
            #pragma unroll
            for (int i = 0; i < 4; i++)
                #pragma unroll
                for (int j = 0; j < 4; j++)
                    sv[i][j] = fmaf(a0[i], b0[j], sv[i][j]);
        }

        #pragma unroll
        for (int i = 0; i < 4; i++) {
            #pragma unroll
            for (int j = 0; j < 4; j++) {
                int kk = kb + tx * 4 + j;
                sv[i][j] = (kk < ng) ? sv[i][j] * 0.125f : -1e30f;
            }
            float cm = fmaxf(fmaxf(sv[i][0], sv[i][1]), fmaxf(sv[i][2], sv[i][3]));
            cm = fmaxf(cm, __shfl_xor_sync(0xffffffffu, cm, 8, 16));
            cm = fmaxf(cm, __shfl_xor_sync(0xffffffffu, cm, 4, 16));
            cm = fmaxf(cm, __shfl_xor_sync(0xffffffffu, cm, 2, 16));
            cm = fmaxf(cm, __shfl_xor_sync(0xffffffffu, cm, 1, 16));
            float nm = fmaxf(rm[i], cm);
            float sc = __expf(rm[i] - nm);
            rm[i] = nm;
            float cl = 0.f;
            #pragma unroll
            for (int j = 0; j < 4; j++) {
                float p = __expf(sv[i][j] - nm);
                sv[i][j] = p;
                cl += p;
            }
            cl += __shfl_xor_sync(0xffffffffu, cl, 8, 16);
            cl += __shfl_xor_sync(0xffffffffu, cl, 4, 16);
            cl += __shfl_xor_sync(0xffffffffu, cl, 2, 16);
            cl += __shfl_xor_sync(0xffffffffu, cl, 1, 16);
            rl[i] = rl[i] * sc + cl;
            #pragma unroll
            for (int j = 0; j < 4; j++) acc[i][j] *= sc;
        }

        #pragma unroll
        for (int i = 0; i < 4; i++)
            #pragma unroll
            for (int j = 0; j < 4; j++)
                Pst[(tx * 4 + j) * APAD + ty * 4 + i] = sv[i][j];
        __syncthreads();

        #pragma unroll
        for (int n = 0; n < 64; n++) {
            float a0[4], b0[4];
            *(float4*)a0 = *(const float4*)&Pst[n * APAD + ty * 4];
            *(float4*)b0 = *(const float4*)&Vsm[n * APAD + tx * 4];
            #pragma unroll
            for (int i = 0; i < 4; i++)
                #pragma unroll
                for (int j = 0; j < 4; j++)
                    acc[i][j] = fmaf(a0[i], b0[j], acc[i][j]);
        }
        __syncthreads();
    }

    #pragma unroll
    for (int i = 0; i < 4; i++) {
        int m = q0 + ty * 4 + i;
        if (m < ng) {
            float inv = 1.f / rl[i];
            float4 o = make_float4(acc[i][0] * inv, acc[i][1] * inv,
                                   acc[i][2] * inv, acc[i][3] * inv);
            *(float4*)&g_o[(size_t)(s0 + m) * DIM + h * DHEAD + tx * 4] = o;
        }
    }
}

// ======================= launch ==================================================
extern "C" void kernel_launch(void* const* d_in, const int* in_sizes, int n_in,
                              void* d_out, int out_size) {
    const float* z     = (const float*)d_in[0];
    const int*   src   = (const int*)  d_in[1];
    const float* gamma = (const float*)d_in[2];
    const float* beta  = (const float*)d_in[3];
    const float* Wq    = (const float*)d_in[4];
    const float* Wk    = (const float*)d_in[5];
    const float* Wv    = (const float*)d_in[6];
    const float* Wo    = (const float*)d_in[7];
    const float* bo    = (const float*)d_in[8];
    float* out = (float*)d_out;

    cudaFuncSetAttribute(attn_kernel, cudaFuncAttributeMaxDynamicSharedMemorySize, ATTN_SMEM);
    cudaFuncSetAttribute(gemm_mma<false>, cudaFuncAttributeMaxDynamicSharedMemorySize, G_SMEM_TOT);
    cudaFuncSetAttribute(gemm_mma<true>,  cudaFuncAttributeMaxDynamicSharedMemorySize, G_SMEM_TOT);

    __nv_bfloat16 *ahi_p, *alo_p, *wthi_p, *wtlo_p;
    float *q_p, *k_p, *v_p, *o_p;
    cudaGetSymbolAddress((void**)&ahi_p,  g_ahi);
    cudaGetSymbolAddress((void**)&alo_p,  g_alo);
    cudaGetSymbolAddress((void**)&wthi_p, g_wthi);
    cudaGetSymbolAddress((void**)&wtlo_p, g_wtlo);
    cudaGetSymbolAddress((void**)&q_p,  g_q);
    cudaGetSymbolAddress((void**)&k_p,  g_k);
    cudaGetSymbolAddress((void**)&v_p,  g_v);
    cudaGetSymbolAddress((void**)&o_p,  g_o);

    starts_kernel<<<1, 64>>>(src);
    ln_kernel<<<NTOT, 128>>>(z, gamma, beta);
    wconv_kernel<<<dim3(16, 16, 4), dim3(32, 8)>>>(Wq, Wk, Wv, Wo);

    // fused Q/K/V projections on tensor cores (legacy HMMA via mma.sync)
    gemm_mma<false><<<dim3(4, 96, 3), 256, G_SMEM_TOT>>>(
        ahi_p, alo_p, wthi_p, wtlo_p, q_p, k_p, v_p, nullptr);

    attn_kernel<<<dim3(NMAXQT, HEADS, NBATCH), 256, ATTN_SMEM>>>();

    oconv_kernel<<<NTOT * DIM / 4 / 256, 256>>>();
    gemm_mma<true><<<dim3(4, 96, 1), 256, G_SMEM_TOT>>>(
        ahi_p, alo_p, wthi_p + 3 * DIN * DIM, wtlo_p + 3 * DIN * DIM,
        out, out, out, bo);
}